// round 13
// baseline (speedup 1.0000x reference)
#include <cuda_runtime.h>
#include <cuda_bf16.h>
#include <cstdint>

#define NB 8
#define PTS 4096
#define NPT (NB*PTS)      // 32768
#define DD 256
#define QT_N 3000
#define QR_N 216
#define PQ 3456           // 27 groups of 128: T[0,3072) R[3072,3328) O[3328,3456)
#define QG 27
#define SROW 264          // smem row stride (bf16): 528B -> rows 4 banks apart, LDSM conflict-free
#define SCALE 0.0625f     // 1/sqrt(256), folded into Qeff (natural domain; poly exp)

// ---------------- device scratch ----------------
__device__ float          g_wv[3][DD];
__device__ float          g_vsum[3][NPT];
__device__ __nv_bfloat16  g_featb[(size_t)NPT*DD];   // 16 MB bf16 feat, row-major
__device__ __nv_bfloat16  g_qeff[(size_t)PQ*DD];     // padded effective queries (scaled)
__device__ float          g_pnum[2][NB*PQ];          // per-half partials (no atomics)
__device__ float          g_pden[2][NB*PQ];

struct TileInfo { int head, rowbase, valid; };
__device__ __forceinline__ TileInfo tile_info(int st) {  // 54 subtiles of 64 padded rows
    TileInfo ti;
    if (st < 48)      { ti.head = 0; ti.rowbase = st*64;      ti.valid = max(0, min(64, QT_N - ti.rowbase)); }
    else if (st < 52) { ti.head = 1; ti.rowbase = (st-48)*64; ti.valid = max(0, min(64, QR_N - ti.rowbase)); }
    else              { ti.head = 2; ti.rowbase = 0;          ti.valid = (st == 52) ? 1 : 0; }
    return ti;
}

// ---------------- K1: wv[h][c] = sum_d Wv_h[c][d] ----------------
__global__ void k_wv(const float* __restrict__ WvT, const float* __restrict__ WvR,
                     const float* __restrict__ WvO) {
    int h  = blockIdx.x >> 3;
    int cg = blockIdx.x & 7;
    const float* W = (h == 0) ? WvT : (h == 1) ? WvR : WvO;
    int w = threadIdx.x >> 5, lane = threadIdx.x & 31;
    #pragma unroll
    for (int i = 0; i < 4; i++) {
        int c = cg*32 + w*4 + i;
        const float* row = W + c*DD;
        float s = 0.f;
        #pragma unroll
        for (int j = 0; j < 8; j++) s += row[lane + j*32];
        #pragma unroll
        for (int o = 16; o > 0; o >>= 1) s += __shfl_xor_sync(0xffffffffu, s, o);
        if (lane == 0) g_wv[h][c] = s;
    }
}

// ---------------- K2: vsum + feat -> bf16 ----------------
__global__ void k_vsum(const float* __restrict__ feat) {
    int gw   = (blockIdx.x*blockDim.x + threadIdx.x) >> 5;  // one warp per point row
    int lane = threadIdx.x & 31;
    const float4* row4 = (const float4*)(feat + (size_t)gw*DD);
    float4 v0 = row4[lane];
    float4 v1 = row4[lane + 32];
    float f0[4] = {v0.x, v0.y, v0.z, v0.w};
    float f1[4] = {v1.x, v1.y, v1.z, v1.w};
    float s[3] = {0.f, 0.f, 0.f};
    int d0 = lane*4;
    #pragma unroll
    for (int i = 0; i < 4; i++) {
        #pragma unroll
        for (int h = 0; h < 3; h++)
            s[h] += f0[i]*g_wv[h][d0+i] + f1[i]*g_wv[h][128+d0+i];
    }
    union { uint2 u; __nv_bfloat16 b[4]; } p0, p1;
    #pragma unroll
    for (int i = 0; i < 4; i++) { p0.b[i] = __float2bfloat16(f0[i]); p1.b[i] = __float2bfloat16(f1[i]); }
    *(uint2*)(g_featb + (size_t)gw*DD + d0)       = p0.u;
    *(uint2*)(g_featb + (size_t)gw*DD + 128 + d0) = p1.u;
    #pragma unroll
    for (int o = 16; o > 0; o >>= 1) {
        #pragma unroll
        for (int h = 0; h < 3; h++) s[h] += __shfl_xor_sync(0xffffffffu, s[h], o);
    }
    if (lane == 0) { g_vsum[0][gw] = s[0]; g_vsum[1][gw] = s[1]; g_vsum[2][gw] = s[2]; }
}

// ---------------- MMA machinery ----------------
__device__ __forceinline__ uint32_t sptr(const void* p) {
    return (uint32_t)__cvta_generic_to_shared(p);
}
__device__ __forceinline__ void ldsm4(uint32_t* r, uint32_t a) {
    asm volatile("ldmatrix.sync.aligned.m8n8.x4.shared.b16 {%0,%1,%2,%3},[%4];"
                 : "=r"(r[0]), "=r"(r[1]), "=r"(r[2]), "=r"(r[3]) : "r"(a));
}
__device__ __forceinline__ void mma16816(float* c, const uint32_t* a, uint32_t b0, uint32_t b1) {
    asm volatile("mma.sync.aligned.m16n8k16.row.col.f32.bf16.bf16.f32 "
                 "{%0,%1,%2,%3},{%4,%5,%6,%7},{%8,%9},{%0,%1,%2,%3};"
                 : "+f"(c[0]), "+f"(c[1]), "+f"(c[2]), "+f"(c[3])
                 : "r"(a[0]), "r"(a[1]), "r"(a[2]), "r"(a[3]), "r"(b0), "r"(b1));
}
// zero-C variant: overwrites acc (no prior zeroing needed)
__device__ __forceinline__ void mma16816z(float* c, const uint32_t* a, uint32_t b0, uint32_t b1) {
    asm volatile("mma.sync.aligned.m16n8k16.row.col.f32.bf16.bf16.f32 "
                 "{%0,%1,%2,%3},{%4,%5,%6,%7},{%8,%9},{%10,%10,%10,%10};"
                 : "=f"(c[0]), "=f"(c[1]), "=f"(c[2]), "=f"(c[3])
                 : "r"(a[0]), "r"(a[1]), "r"(a[2]), "r"(a[3]), "r"(b0), "r"(b1), "f"(0.f));
}
__device__ __forceinline__ unsigned long long pk2(float lo, float hi) {
    unsigned long long r; asm("mov.b64 %0,{%1,%2};" : "=l"(r) : "f"(lo), "f"(hi)); return r;
}
__device__ __forceinline__ void upk2(float& lo, float& hi, unsigned long long v) {
    asm("mov.b64 {%0,%1},%2;" : "=f"(lo), "=f"(hi) : "l"(v));
}
__device__ __forceinline__ unsigned long long add2(unsigned long long a, unsigned long long b) {
    unsigned long long r; asm("add.rn.f32x2 %0,%1,%2;" : "=l"(r) : "l"(a), "l"(b)); return r;
}
__device__ __forceinline__ unsigned long long fma2(unsigned long long a, unsigned long long b,
                                                   unsigned long long c) {
    unsigned long long r; asm("fma.rn.f32x2 %0,%1,%2,%3;" : "=l"(r) : "l"(a), "l"(b), "l"(c)); return r;
}
__device__ __forceinline__ void cpa16(uint32_t dst, const void* src) {
    asm volatile("cp.async.cg.shared.global [%0],[%1],16;" :: "r"(dst), "l"(src) : "memory");
}
__device__ __forceinline__ void cpa_commit() { asm volatile("cp.async.commit_group;" ::: "memory"); }
template<int N> __device__ __forceinline__ void cpa_wait() {
    asm volatile("cp.async.wait_group %0;" :: "n"(N) : "memory");
}

// small gemm for k_qeff (64x64 tile, warp m32 x n16)
__device__ __forceinline__ void gemm64(const __nv_bfloat16* sa, const __nv_bfloat16* sb,
                                       float acc[2][2][4], int wm, int wn, int lane) {
    int arow = lane & 15, acol = (lane >> 4) << 3;
    uint32_t abase0 = sptr(sa + (wm*32 + arow)*SROW + acol);
    uint32_t abase1 = abase0 + 16*SROW*2;
    int brow = ((lane >> 4) & 1)*8 + (lane & 7);
    int bcol = ((lane >> 3) & 1) << 3;
    uint32_t bbase = sptr(sb + (wn*16 + brow)*SROW + bcol);
    #pragma unroll
    for (int k0 = 0; k0 < DD; k0 += 16) {
        uint32_t A0[4], A1[4], Bv[4];
        ldsm4(A0, abase0 + k0*2);
        ldsm4(A1, abase1 + k0*2);
        ldsm4(Bv, bbase  + k0*2);
        mma16816(acc[0][0], A0, Bv[0], Bv[1]);
        mma16816(acc[0][1], A0, Bv[2], Bv[3]);
        mma16816(acc[1][0], A1, Bv[0], Bv[1]);
        mma16816(acc[1][1], A1, Bv[2], Bv[3]);
    }
}

// ---------------- K3: Qeff (queries @ Wk^T, scaled, padded, linear layout) ----------------
__global__ void __launch_bounds__(256) k_qeff(const float* __restrict__ qTp, const float* __restrict__ WkT,
                                              const float* __restrict__ qRp, const float* __restrict__ WkR,
                                              const float* __restrict__ qOp, const float* __restrict__ WkO) {
    extern __shared__ __nv_bfloat16 sm3[];
    __nv_bfloat16* sa = sm3;
    __nv_bfloat16* sb = sm3 + 64*SROW;
    int st = blockIdx.x, ct = blockIdx.y;
    TileInfo ti = tile_info(st);
    const float* Q  = (ti.head == 0) ? qTp : (ti.head == 1) ? qRp : qOp;
    const float* Wk = (ti.head == 0) ? WkT : (ti.head == 1) ? WkR : WkO;
    int tid = threadIdx.x;
    #pragma unroll 4
    for (int i = tid; i < 64*64; i += 256) {
        int r = i >> 6, c4 = (i & 63) << 2;
        float4 qv = make_float4(0.f, 0.f, 0.f, 0.f);
        if (r < ti.valid) qv = *(const float4*)(Q + (size_t)(ti.rowbase + r)*DD + c4);
        float4 wv = *(const float4*)(Wk + (size_t)(ct*64 + r)*DD + c4);
        union { uint2 u; __nv_bfloat16 b[4]; } pq, pw;
        pq.b[0] = __float2bfloat16(qv.x); pq.b[1] = __float2bfloat16(qv.y);
        pq.b[2] = __float2bfloat16(qv.z); pq.b[3] = __float2bfloat16(qv.w);
        pw.b[0] = __float2bfloat16(wv.x); pw.b[1] = __float2bfloat16(wv.y);
        pw.b[2] = __float2bfloat16(wv.z); pw.b[3] = __float2bfloat16(wv.w);
        *(uint2*)(sa + r*SROW + c4) = pq.u;
        *(uint2*)(sb + r*SROW + c4) = pw.u;
    }
    __syncthreads();
    int lane = tid & 31, w = tid >> 5, wm = w >> 2, wn = w & 3;
    float acc[2][2][4];
    #pragma unroll
    for (int a = 0; a < 2; a++)
        #pragma unroll
        for (int b2 = 0; b2 < 2; b2++)
            #pragma unroll
            for (int c = 0; c < 4; c++) acc[a][b2][c] = 0.f;
    gemm64(sa, sb, acc, wm, wn, lane);
    int g2 = lane >> 2, t = lane & 3;
    #pragma unroll
    for (int mi = 0; mi < 2; mi++)
        #pragma unroll
        for (int nj = 0; nj < 2; nj++) {
            int cc = ct*64 + wn*16 + nj*8 + 2*t;
            int p0 = st*64 + wm*32 + mi*16 + g2;
            __nv_bfloat162 lo, hi;
            lo.x = __float2bfloat16(acc[mi][nj][0]*SCALE);
            lo.y = __float2bfloat16(acc[mi][nj][1]*SCALE);
            hi.x = __float2bfloat16(acc[mi][nj][2]*SCALE);
            hi.y = __float2bfloat16(acc[mi][nj][3]*SCALE);
            *(__nv_bfloat162*)(g_qeff + (size_t)p0*DD + cc)     = lo;
            *(__nv_bfloat162*)(g_qeff + (size_t)(p0+8)*DD + cc) = hi;
        }
}

// ---------------- K4: 256 threads, 8 warps (2m x 4n), warp tile m64n32 ----------------
// fragment double-buffered k-loop: LDSM batch kk+1 issued before MMAs of kk
// smem layout (bytes)
#define QE_OFF    0u
#define FB_OFF(s) (67584u + (uint32_t)(s)*67584u)
#define VS_OFF(s) (202752u + (uint32_t)(s)*512u)
#define RED_OFF   203776u    // rn[2][128] + rd[2][128] = 2048 B
#define SMEM_MAIN 205824

__device__ __forceinline__ void load_tile(uint32_t sdst, const __nv_bfloat16* gsrc, int tid) {
    #pragma unroll
    for (int i = 0; i < 16; i++) {
        int idx = tid + i*256;
        int r = idx >> 5, c = idx & 31;
        cpa16(sdst + (uint32_t)(r*SROW + c*8)*2, gsrc + r*DD + c*8);
    }
}

#define ONE2  0x3F8000003F800000ull
#define HALF2 0x3F0000003F000000ull

// epilogue for one acc cell: poly exp e = 1 + s + s^2/2, packed f32x2
__device__ __forceinline__ void epi_cell(const float* cell, int mi, int nj,
                                         const float* vP,
                                         unsigned long long* num2, unsigned long long* den2) {
    unsigned long long s01 = pk2(cell[0], cell[1]);
    unsigned long long s23 = pk2(cell[2], cell[3]);
    unsigned long long e01 = fma2(s01, fma2(s01, HALF2, ONE2), ONE2);
    unsigned long long e23 = fma2(s23, fma2(s23, HALF2, ONE2), ONE2);
    unsigned long long v0 = pk2(vP[mi*2+0], vP[mi*2+0]);
    unsigned long long v1 = pk2(vP[mi*2+1], vP[mi*2+1]);
    den2[nj] = add2(den2[nj], e01);
    num2[nj] = fma2(e01, v0, num2[nj]);
    den2[nj] = add2(den2[nj], e23);
    num2[nj] = fma2(e23, v1, num2[nj]);
}

__device__ __forceinline__ void ld_frags(uint32_t abase, uint32_t bbase, int kk,
                                         uint32_t A[4][4], uint32_t B[2][4]) {
    #pragma unroll
    for (int mi = 0; mi < 4; mi++) ldsm4(A[mi], abase + (uint32_t)(mi*16*SROW + kk*16)*2);
    #pragma unroll
    for (int nb = 0; nb < 2; nb++) ldsm4(B[nb], bbase + (uint32_t)(nb*16*SROW + kk*16)*2);
}

__global__ void __launch_bounds__(256, 1) k_main() {
    extern __shared__ unsigned char sm[];
    uint32_t smb = sptr(sm);
    int qg = blockIdx.x, b = blockIdx.y, half = blockIdx.z;
    int tid = threadIdx.x, lane = tid & 31, wid = tid >> 5;
    int wm = wid >> 2, wn = wid & 3, g2 = lane >> 2;
    int base = b*PTS + half*2048;          // first point row of this CTA
    int head = (qg < 24) ? 0 : ((qg < 26) ? 1 : 2);   // uniform per q-group
    const float* vsrc = g_vsum[head];

    // prologue: q tile + chunk0 (one group)
    load_tile(smb + QE_OFF, g_qeff + (size_t)qg*128*DD, tid);
    load_tile(smb + FB_OFF(0), g_featb + (size_t)base*DD, tid);
    if (tid < 32) cpa16(smb + VS_OFF(0) + (uint32_t)tid*16, vsrc + base + tid*4);
    cpa_commit();

    unsigned long long num2[4], den2[4];
    #pragma unroll
    for (int i = 0; i < 4; i++) { num2[i] = 0ull; den2[i] = 0ull; }

    // fragment addresses: warp tile m64 (rows wm*64..+63), n32 (q rows wn*32..+31)
    uint32_t aoff = (uint32_t)((wm*64 + (lane & 15))*SROW + ((lane >> 4) << 3))*2;
    int brow = ((lane >> 4) & 1)*8 + (lane & 7);
    int bcol = ((lane >> 3) & 1) << 3;
    uint32_t bbase = smb + QE_OFF + (uint32_t)((wn*32 + brow)*SROW + bcol)*2;

    #pragma unroll 1
    for (int c = 0; c < 16; c++) {
        int s = c & 1;
        cpa_wait<0>();       // chunk c's data arrived
        __syncthreads();     // + all warps done with buffer s^1 (chunk c-1)
        if (c + 1 < 16) {    // prefetch chunk c+1 into the other buffer
            load_tile(smb + FB_OFF(s ^ 1), g_featb + (size_t)(base + (c + 1)*128)*DD, tid);
            if (tid < 32) cpa16(smb + VS_OFF(s ^ 1) + (uint32_t)tid*16, vsrc + base + (c + 1)*128 + tid*4);
            cpa_commit();
        }
        // vsum rows for this warp's 8 row-slots
        const float* vbuf = (const float*)(sm + VS_OFF(s));
        float vC[8];
        #pragma unroll
        for (int ri = 0; ri < 8; ri++)
            vC[ri] = vbuf[wm*64 + (ri >> 1)*16 + (ri & 1)*8 + g2];

        float acc[4][4][4];
        uint32_t abase = smb + FB_OFF(s) + aoff;
        uint32_t Aq[2][4][4], Bq[2][2][4];
        ld_frags(abase, bbase, 0, Aq[0], Bq[0]);
        #pragma unroll
        for (int kk = 0; kk < 16; kk++) {
            int cur = kk & 1, nxt = cur ^ 1;
            if (kk < 15) ld_frags(abase, bbase, kk + 1, Aq[nxt], Bq[nxt]);
            #pragma unroll
            for (int mi = 0; mi < 4; mi++)
                #pragma unroll
                for (int nb = 0; nb < 2; nb++) {
                    if (kk == 0) {
                        mma16816z(acc[mi][nb*2+0], Aq[cur][mi], Bq[cur][nb][0], Bq[cur][nb][1]);
                        mma16816z(acc[mi][nb*2+1], Aq[cur][mi], Bq[cur][nb][2], Bq[cur][nb][3]);
                    } else {
                        mma16816(acc[mi][nb*2+0], Aq[cur][mi], Bq[cur][nb][0], Bq[cur][nb][1]);
                        mma16816(acc[mi][nb*2+1], Aq[cur][mi], Bq[cur][nb][2], Bq[cur][nb][3]);
                    }
                }
        }
        // epilogue: 16 cells
        #pragma unroll
        for (int mi = 0; mi < 4; mi++)
            #pragma unroll
            for (int nj = 0; nj < 4; nj++)
                epi_cell(acc[mi][nj], mi, nj, vC, num2, den2);
    }

    // unpack; reduce over 8 lanes sharing each column (xor 4,8,16 over g2)
    float num[8], den[8];
    #pragma unroll
    for (int nj = 0; nj < 4; nj++) {
        upk2(num[nj*2], num[nj*2+1], num2[nj]);
        upk2(den[nj*2], den[nj*2+1], den2[nj]);
    }
    #pragma unroll
    for (int o = 4; o < 32; o <<= 1) {
        #pragma unroll
        for (int i = 0; i < 8; i++) {
            num[i] += __shfl_xor_sync(0xffffffffu, num[i], o);
            den[i] += __shfl_xor_sync(0xffffffffu, den[i], o);
        }
    }
    __syncthreads();
    float* rn = (float*)(sm + RED_OFF);   // [2][128]
    float* rd = rn + 256;                 // [2][128]
    if (lane < 4) {
        #pragma unroll
        for (int i = 0; i < 8; i++) {
            int col = wn*32 + (i >> 1)*8 + 2*lane + (i & 1);
            rn[wm*128 + col] = num[i];
            rd[wm*128 + col] = den[i];
        }
    }
    __syncthreads();
    if (tid < 128) {
        g_pnum[half][b*PQ + qg*128 + tid] = rn[tid] + rn[128 + tid];
    } else if (tid < 256) {
        int col = tid - 128;
        g_pden[half][b*PQ + qg*128 + col] = rd[col] + rd[128 + col];
    }
}

// ---------------- K5: combine halves + divide + scatter ----------------
__global__ void k_final(float* __restrict__ out) {
    int i = blockIdx.x*256 + threadIdx.x;
    if (i >= NB*PQ) return;
    int b = i / PQ, p = i % PQ;
    float nsum = g_pnum[0][i] + g_pnum[1][i];
    float dsum = g_pden[0][i] + g_pden[1][i];
    float r = nsum / dsum;
    if (p < QT_N)                    out[b*QT_N + p] = r;
    else if (p >= 3072 && p < 3288)  out[NB*QT_N + b*QR_N + (p - 3072)] = r;
    else if (p == 3328)              out[NB*QT_N + NB*QR_N + b] = r;
}

// ---------------- launch ----------------
extern "C" void kernel_launch(void* const* d_in, const int* in_sizes, int n_in,
                              void* d_out, int out_size) {
    const float* feat = (const float*)d_in[0];
    const float* qT  = (const float*)d_in[2];
    const float* WkT = (const float*)d_in[3];
    const float* WvT = (const float*)d_in[4];
    const float* qR  = (const float*)d_in[5];
    const float* WkR = (const float*)d_in[6];
    const float* WvR = (const float*)d_in[7];
    const float* qO  = (const float*)d_in[8];
    const float* WkO = (const float*)d_in[9];
    const float* WvO = (const float*)d_in[10];
    float* out = (float*)d_out;

    const int smem3 = 2 * 64 * SROW * (int)sizeof(__nv_bfloat16);
    cudaFuncSetAttribute(k_qeff, cudaFuncAttributeMaxDynamicSharedMemorySize, smem3);
    cudaFuncSetAttribute(k_main, cudaFuncAttributeMaxDynamicSharedMemorySize, SMEM_MAIN);

    k_wv  <<<24, 256>>>(WvT, WvR, WvO);
    k_vsum<<<NPT/8, 256>>>(feat);
    k_qeff<<<dim3(54, 4), 256, smem3>>>(qT, WkT, qR, WkR, qO, WkO);
    k_main<<<dim3(QG, NB, 2), 256, SMEM_MAIN>>>();
    k_final<<<(NB*PQ + 255)/256, 256>>>(out);
}

// round 14
// speedup vs baseline: 1.0442x; 1.0442x over previous
#include <cuda_runtime.h>
#include <cuda_bf16.h>
#include <cstdint>

#define NB 8
#define PTS 4096
#define NPT (NB*PTS)      // 32768
#define DD 256
#define QT_N 3000
#define QR_N 216
#define PQ 3456           // 27 groups of 128: T[0,3072) R[3072,3328) O[3328,3456)
#define QG 27
#define SROW 264          // smem row stride (bf16): 528B -> rows 4 banks apart, LDSM conflict-free
#define SCALE 0.0625f     // 1/sqrt(256), folded into Qeff (natural domain; poly exp)

// ---------------- device scratch ----------------
__device__ float          g_wv[3][DD];
__device__ float          g_vsum[3][NPT];
__device__ __nv_bfloat16  g_featb[(size_t)NPT*DD];   // 16 MB bf16 feat, row-major
__device__ __nv_bfloat16  g_qeff[(size_t)PQ*DD];     // padded effective queries (scaled)
__device__ float          g_pnum[2][NB*PQ];          // per-half partials (no atomics)
__device__ float          g_pden[2][NB*PQ];

struct TileInfo { int head, rowbase, valid; };
__device__ __forceinline__ TileInfo tile_info(int st) {  // 54 subtiles of 64 padded rows
    TileInfo ti;
    if (st < 48)      { ti.head = 0; ti.rowbase = st*64;      ti.valid = max(0, min(64, QT_N - ti.rowbase)); }
    else if (st < 52) { ti.head = 1; ti.rowbase = (st-48)*64; ti.valid = max(0, min(64, QR_N - ti.rowbase)); }
    else              { ti.head = 2; ti.rowbase = 0;          ti.valid = (st == 52) ? 1 : 0; }
    return ti;
}

// ---------------- K1: wv[h][c] = sum_d Wv_h[c][d] ----------------
__global__ void k_wv(const float* __restrict__ WvT, const float* __restrict__ WvR,
                     const float* __restrict__ WvO) {
    int h  = blockIdx.x >> 3;
    int cg = blockIdx.x & 7;
    const float* W = (h == 0) ? WvT : (h == 1) ? WvR : WvO;
    int w = threadIdx.x >> 5, lane = threadIdx.x & 31;
    #pragma unroll
    for (int i = 0; i < 4; i++) {
        int c = cg*32 + w*4 + i;
        const float* row = W + c*DD;
        float s = 0.f;
        #pragma unroll
        for (int j = 0; j < 8; j++) s += row[lane + j*32];
        #pragma unroll
        for (int o = 16; o > 0; o >>= 1) s += __shfl_xor_sync(0xffffffffu, s, o);
        if (lane == 0) g_wv[h][c] = s;
    }
}

// ---------------- K2: vsum + feat -> bf16 ----------------
__global__ void k_vsum(const float* __restrict__ feat) {
    int gw   = (blockIdx.x*blockDim.x + threadIdx.x) >> 5;  // one warp per point row
    int lane = threadIdx.x & 31;
    const float4* row4 = (const float4*)(feat + (size_t)gw*DD);
    float4 v0 = row4[lane];
    float4 v1 = row4[lane + 32];
    float f0[4] = {v0.x, v0.y, v0.z, v0.w};
    float f1[4] = {v1.x, v1.y, v1.z, v1.w};
    float s[3] = {0.f, 0.f, 0.f};
    int d0 = lane*4;
    #pragma unroll
    for (int i = 0; i < 4; i++) {
        #pragma unroll
        for (int h = 0; h < 3; h++)
            s[h] += f0[i]*g_wv[h][d0+i] + f1[i]*g_wv[h][128+d0+i];
    }
    union { uint2 u; __nv_bfloat16 b[4]; } p0, p1;
    #pragma unroll
    for (int i = 0; i < 4; i++) { p0.b[i] = __float2bfloat16(f0[i]); p1.b[i] = __float2bfloat16(f1[i]); }
    *(uint2*)(g_featb + (size_t)gw*DD + d0)       = p0.u;
    *(uint2*)(g_featb + (size_t)gw*DD + 128 + d0) = p1.u;
    #pragma unroll
    for (int o = 16; o > 0; o >>= 1) {
        #pragma unroll
        for (int h = 0; h < 3; h++) s[h] += __shfl_xor_sync(0xffffffffu, s[h], o);
    }
    if (lane == 0) { g_vsum[0][gw] = s[0]; g_vsum[1][gw] = s[1]; g_vsum[2][gw] = s[2]; }
}

// ---------------- MMA machinery ----------------
__device__ __forceinline__ uint32_t sptr(const void* p) {
    return (uint32_t)__cvta_generic_to_shared(p);
}
__device__ __forceinline__ void ldsm4(uint32_t* r, uint32_t a) {
    asm volatile("ldmatrix.sync.aligned.m8n8.x4.shared.b16 {%0,%1,%2,%3},[%4];"
                 : "=r"(r[0]), "=r"(r[1]), "=r"(r[2]), "=r"(r[3]) : "r"(a));
}
__device__ __forceinline__ void mma16816(float* c, const uint32_t* a, uint32_t b0, uint32_t b1) {
    asm volatile("mma.sync.aligned.m16n8k16.row.col.f32.bf16.bf16.f32 "
                 "{%0,%1,%2,%3},{%4,%5,%6,%7},{%8,%9},{%0,%1,%2,%3};"
                 : "+f"(c[0]), "+f"(c[1]), "+f"(c[2]), "+f"(c[3])
                 : "r"(a[0]), "r"(a[1]), "r"(a[2]), "r"(a[3]), "r"(b0), "r"(b1));
}
// zero-C variant: overwrites acc (no prior zeroing needed)
__device__ __forceinline__ void mma16816z(float* c, const uint32_t* a, uint32_t b0, uint32_t b1) {
    asm volatile("mma.sync.aligned.m16n8k16.row.col.f32.bf16.bf16.f32 "
                 "{%0,%1,%2,%3},{%4,%5,%6,%7},{%8,%9},{%10,%10,%10,%10};"
                 : "=f"(c[0]), "=f"(c[1]), "=f"(c[2]), "=f"(c[3])
                 : "r"(a[0]), "r"(a[1]), "r"(a[2]), "r"(a[3]), "r"(b0), "r"(b1), "f"(0.f));
}
__device__ __forceinline__ unsigned long long pk2(float lo, float hi) {
    unsigned long long r; asm("mov.b64 %0,{%1,%2};" : "=l"(r) : "f"(lo), "f"(hi)); return r;
}
__device__ __forceinline__ void upk2(float& lo, float& hi, unsigned long long v) {
    asm("mov.b64 {%0,%1},%2;" : "=f"(lo), "=f"(hi) : "l"(v));
}
__device__ __forceinline__ unsigned long long add2(unsigned long long a, unsigned long long b) {
    unsigned long long r; asm("add.rn.f32x2 %0,%1,%2;" : "=l"(r) : "l"(a), "l"(b)); return r;
}
__device__ __forceinline__ unsigned long long fma2(unsigned long long a, unsigned long long b,
                                                   unsigned long long c) {
    unsigned long long r; asm("fma.rn.f32x2 %0,%1,%2,%3;" : "=l"(r) : "l"(a), "l"(b), "l"(c)); return r;
}
__device__ __forceinline__ void cpa16(uint32_t dst, const void* src) {
    asm volatile("cp.async.cg.shared.global [%0],[%1],16;" :: "r"(dst), "l"(src) : "memory");
}
__device__ __forceinline__ void cpa_commit() { asm volatile("cp.async.commit_group;" ::: "memory"); }
template<int N> __device__ __forceinline__ void cpa_wait() {
    asm volatile("cp.async.wait_group %0;" :: "n"(N) : "memory");
}

// small gemm for k_qeff (64x64 tile, warp m32 x n16)
__device__ __forceinline__ void gemm64(const __nv_bfloat16* sa, const __nv_bfloat16* sb,
                                       float acc[2][2][4], int wm, int wn, int lane) {
    int arow = lane & 15, acol = (lane >> 4) << 3;
    uint32_t abase0 = sptr(sa + (wm*32 + arow)*SROW + acol);
    uint32_t abase1 = abase0 + 16*SROW*2;
    int brow = ((lane >> 4) & 1)*8 + (lane & 7);
    int bcol = ((lane >> 3) & 1) << 3;
    uint32_t bbase = sptr(sb + (wn*16 + brow)*SROW + bcol);
    #pragma unroll
    for (int k0 = 0; k0 < DD; k0 += 16) {
        uint32_t A0[4], A1[4], Bv[4];
        ldsm4(A0, abase0 + k0*2);
        ldsm4(A1, abase1 + k0*2);
        ldsm4(Bv, bbase  + k0*2);
        mma16816(acc[0][0], A0, Bv[0], Bv[1]);
        mma16816(acc[0][1], A0, Bv[2], Bv[3]);
        mma16816(acc[1][0], A1, Bv[0], Bv[1]);
        mma16816(acc[1][1], A1, Bv[2], Bv[3]);
    }
}

// ---------------- K3: Qeff (queries @ Wk^T, scaled, padded, linear layout) ----------------
__global__ void __launch_bounds__(256) k_qeff(const float* __restrict__ qTp, const float* __restrict__ WkT,
                                              const float* __restrict__ qRp, const float* __restrict__ WkR,
                                              const float* __restrict__ qOp, const float* __restrict__ WkO) {
    extern __shared__ __nv_bfloat16 sm3[];
    __nv_bfloat16* sa = sm3;
    __nv_bfloat16* sb = sm3 + 64*SROW;
    int st = blockIdx.x, ct = blockIdx.y;
    TileInfo ti = tile_info(st);
    const float* Q  = (ti.head == 0) ? qTp : (ti.head == 1) ? qRp : qOp;
    const float* Wk = (ti.head == 0) ? WkT : (ti.head == 1) ? WkR : WkO;
    int tid = threadIdx.x;
    #pragma unroll 4
    for (int i = tid; i < 64*64; i += 256) {
        int r = i >> 6, c4 = (i & 63) << 2;
        float4 qv = make_float4(0.f, 0.f, 0.f, 0.f);
        if (r < ti.valid) qv = *(const float4*)(Q + (size_t)(ti.rowbase + r)*DD + c4);
        float4 wv = *(const float4*)(Wk + (size_t)(ct*64 + r)*DD + c4);
        union { uint2 u; __nv_bfloat16 b[4]; } pq, pw;
        pq.b[0] = __float2bfloat16(qv.x); pq.b[1] = __float2bfloat16(qv.y);
        pq.b[2] = __float2bfloat16(qv.z); pq.b[3] = __float2bfloat16(qv.w);
        pw.b[0] = __float2bfloat16(wv.x); pw.b[1] = __float2bfloat16(wv.y);
        pw.b[2] = __float2bfloat16(wv.z); pw.b[3] = __float2bfloat16(wv.w);
        *(uint2*)(sa + r*SROW + c4) = pq.u;
        *(uint2*)(sb + r*SROW + c4) = pw.u;
    }
    __syncthreads();
    int lane = tid & 31, w = tid >> 5, wm = w >> 2, wn = w & 3;
    float acc[2][2][4];
    #pragma unroll
    for (int a = 0; a < 2; a++)
        #pragma unroll
        for (int b2 = 0; b2 < 2; b2++)
            #pragma unroll
            for (int c = 0; c < 4; c++) acc[a][b2][c] = 0.f;
    gemm64(sa, sb, acc, wm, wn, lane);
    int g2 = lane >> 2, t = lane & 3;
    #pragma unroll
    for (int mi = 0; mi < 2; mi++)
        #pragma unroll
        for (int nj = 0; nj < 2; nj++) {
            int cc = ct*64 + wn*16 + nj*8 + 2*t;
            int p0 = st*64 + wm*32 + mi*16 + g2;
            __nv_bfloat162 lo, hi;
            lo.x = __float2bfloat16(acc[mi][nj][0]*SCALE);
            lo.y = __float2bfloat16(acc[mi][nj][1]*SCALE);
            hi.x = __float2bfloat16(acc[mi][nj][2]*SCALE);
            hi.y = __float2bfloat16(acc[mi][nj][3]*SCALE);
            *(__nv_bfloat162*)(g_qeff + (size_t)p0*DD + cc)     = lo;
            *(__nv_bfloat162*)(g_qeff + (size_t)(p0+8)*DD + cc) = hi;
        }
}

// ---------------- K4: 256 threads, 8 warps (2m x 4n), warp tile m64n32 ----------------
// fragment double-buffered k-loop: LDSM batch kk+1 issued before MMAs of kk
// smem layout (bytes)
#define QE_OFF    0u
#define FB_OFF(s) (67584u + (uint32_t)(s)*67584u)
#define VS_OFF(s) (202752u + (uint32_t)(s)*512u)
#define RED_OFF   203776u    // rn[2][128] + rd[2][128] = 2048 B
#define SMEM_MAIN 205824

__device__ __forceinline__ void load_tile(uint32_t sdst, const __nv_bfloat16* gsrc, int tid) {
    #pragma unroll
    for (int i = 0; i < 16; i++) {
        int idx = tid + i*256;
        int r = idx >> 5, c = idx & 31;
        cpa16(sdst + (uint32_t)(r*SROW + c*8)*2, gsrc + r*DD + c*8);
    }
}

#define ONE2  0x3F8000003F800000ull
#define HALF2 0x3F0000003F000000ull

// epilogue for one acc cell: poly exp e = 1 + s + s^2/2, packed f32x2
__device__ __forceinline__ void epi_cell(const float* cell, int mi, int nj,
                                         const float* vP,
                                         unsigned long long* num2, unsigned long long* den2) {
    unsigned long long s01 = pk2(cell[0], cell[1]);
    unsigned long long s23 = pk2(cell[2], cell[3]);
    unsigned long long e01 = fma2(s01, fma2(s01, HALF2, ONE2), ONE2);
    unsigned long long e23 = fma2(s23, fma2(s23, HALF2, ONE2), ONE2);
    unsigned long long v0 = pk2(vP[mi*2+0], vP[mi*2+0]);
    unsigned long long v1 = pk2(vP[mi*2+1], vP[mi*2+1]);
    den2[nj] = add2(den2[nj], e01);
    num2[nj] = fma2(e01, v0, num2[nj]);
    den2[nj] = add2(den2[nj], e23);
    num2[nj] = fma2(e23, v1, num2[nj]);
}

__device__ __forceinline__ void ld_frags(uint32_t abase, uint32_t bbase, int kk,
                                         uint32_t A[4][4], uint32_t B[2][4]) {
    #pragma unroll
    for (int mi = 0; mi < 4; mi++) ldsm4(A[mi], abase + (uint32_t)(mi*16*SROW + kk*16)*2);
    #pragma unroll
    for (int nb = 0; nb < 2; nb++) ldsm4(B[nb], bbase + (uint32_t)(nb*16*SROW + kk*16)*2);
}

__global__ void __launch_bounds__(256, 1) k_main() {
    extern __shared__ unsigned char sm[];
    uint32_t smb = sptr(sm);
    int qg = blockIdx.x, b = blockIdx.y, half = blockIdx.z;
    int tid = threadIdx.x, lane = tid & 31, wid = tid >> 5;
    int wm = wid >> 2, wn = wid & 3, g2 = lane >> 2;
    int base = b*PTS + half*2048;          // first point row of this CTA
    int head = (qg < 24) ? 0 : ((qg < 26) ? 1 : 2);   // uniform per q-group
    const float* vsrc = g_vsum[head];

    // prologue: q tile + chunk0 (one group)
    load_tile(smb + QE_OFF, g_qeff + (size_t)qg*128*DD, tid);
    load_tile(smb + FB_OFF(0), g_featb + (size_t)base*DD, tid);
    if (tid < 32) cpa16(smb + VS_OFF(0) + (uint32_t)tid*16, vsrc + base + tid*4);
    cpa_commit();

    unsigned long long num2[4], den2[4];
    #pragma unroll
    for (int i = 0; i < 4; i++) { num2[i] = 0ull; den2[i] = 0ull; }

    // fragment addresses: warp tile m64 (rows wm*64..+63), n32 (q rows wn*32..+31)
    uint32_t aoff = (uint32_t)((wm*64 + (lane & 15))*SROW + ((lane >> 4) << 3))*2;
    int brow = ((lane >> 4) & 1)*8 + (lane & 7);
    int bcol = ((lane >> 3) & 1) << 3;
    uint32_t bbase = smb + QE_OFF + (uint32_t)((wn*32 + brow)*SROW + bcol)*2;

    #pragma unroll 1
    for (int c = 0; c < 16; c++) {
        int s = c & 1;
        cpa_wait<0>();       // chunk c's data arrived
        __syncthreads();     // + all warps done with buffer s^1 (chunk c-1)
        if (c + 1 < 16) {    // prefetch chunk c+1 into the other buffer
            load_tile(smb + FB_OFF(s ^ 1), g_featb + (size_t)(base + (c + 1)*128)*DD, tid);
            if (tid < 32) cpa16(smb + VS_OFF(s ^ 1) + (uint32_t)tid*16, vsrc + base + (c + 1)*128 + tid*4);
            cpa_commit();
        }
        // vsum rows for this warp's 8 row-slots
        const float* vbuf = (const float*)(sm + VS_OFF(s));
        float vC[8];
        #pragma unroll
        for (int ri = 0; ri < 8; ri++)
            vC[ri] = vbuf[wm*64 + (ri >> 1)*16 + (ri & 1)*8 + g2];

        float acc[4][4][4];
        uint32_t abase = smb + FB_OFF(s) + aoff;
        uint32_t Aq[2][4][4], Bq[2][2][4];
        ld_frags(abase, bbase, 0, Aq[0], Bq[0]);
        #pragma unroll
        for (int kk = 0; kk < 16; kk++) {
            int cur = kk & 1, nxt = cur ^ 1;
            if (kk < 15) ld_frags(abase, bbase, kk + 1, Aq[nxt], Bq[nxt]);
            #pragma unroll
            for (int mi = 0; mi < 4; mi++)
                #pragma unroll
                for (int nb = 0; nb < 2; nb++) {
                    if (kk == 0) {
                        mma16816z(acc[mi][nb*2+0], Aq[cur][mi], Bq[cur][nb][0], Bq[cur][nb][1]);
                        mma16816z(acc[mi][nb*2+1], Aq[cur][mi], Bq[cur][nb][2], Bq[cur][nb][3]);
                    } else {
                        mma16816(acc[mi][nb*2+0], Aq[cur][mi], Bq[cur][nb][0], Bq[cur][nb][1]);
                        mma16816(acc[mi][nb*2+1], Aq[cur][mi], Bq[cur][nb][2], Bq[cur][nb][3]);
                    }
                }
        }
        // epilogue: 16 cells
        #pragma unroll
        for (int mi = 0; mi < 4; mi++)
            #pragma unroll
            for (int nj = 0; nj < 4; nj++)
                epi_cell(acc[mi][nj], mi, nj, vC, num2, den2);
    }

    // unpack; reduce over 8 lanes sharing each column (xor 4,8,16 over g2)
    float num[8], den[8];
    #pragma unroll
    for (int nj = 0; nj < 4; nj++) {
        upk2(num[nj*2], num[nj*2+1], num2[nj]);
        upk2(den[nj*2], den[nj*2+1], den2[nj]);
    }
    #pragma unroll
    for (int o = 4; o < 32; o <<= 1) {
        #pragma unroll
        for (int i = 0; i < 8; i++) {
            num[i] += __shfl_xor_sync(0xffffffffu, num[i], o);
            den[i] += __shfl_xor_sync(0xffffffffu, den[i], o);
        }
    }
    __syncthreads();
    float* rn = (float*)(sm + RED_OFF);   // [2][128]
    float* rd = rn + 256;                 // [2][128]
    if (lane < 4) {
        #pragma unroll
        for (int i = 0; i < 8; i++) {
            int col = wn*32 + (i >> 1)*8 + 2*lane + (i & 1);
            rn[wm*128 + col] = num[i];
            rd[wm*128 + col] = den[i];
        }
    }
    __syncthreads();
    if (tid < 128) {
        g_pnum[half][b*PQ + qg*128 + tid] = rn[tid] + rn[128 + tid];
    } else if (tid < 256) {
        int col = tid - 128;
        g_pden[half][b*PQ + qg*128 + col] = rd[col] + rd[128 + col];
    }
}

// ---------------- K5: combine halves + divide + scatter ----------------
__global__ void k_final(float* __restrict__ out) {
    int i = blockIdx.x*256 + threadIdx.x;
    if (i >= NB*PQ) return;
    int b = i / PQ, p = i % PQ;
    float nsum = g_pnum[0][i] + g_pnum[1][i];
    float dsum = g_pden[0][i] + g_pden[1][i];
    float r = nsum / dsum;
    if (p < QT_N)                    out[b*QT_N + p] = r;
    else if (p >= 3072 && p < 3288)  out[NB*QT_N + b*QR_N + (p - 3072)] = r;
    else if (p == 3328)              out[NB*QT_N + NB*QR_N + b] = r;
}

// ---------------- launch ----------------
extern "C" void kernel_launch(void* const* d_in, const int* in_sizes, int n_in,
                              void* d_out, int out_size) {
    const float* feat = (const float*)d_in[0];
    const float* qT  = (const float*)d_in[2];
    const float* WkT = (const float*)d_in[3];
    const float* WvT = (const float*)d_in[4];
    const float* qR  = (const float*)d_in[5];
    const float* WkR = (const float*)d_in[6];
    const float* WvR = (const float*)d_in[7];
    const float* qO  = (const float*)d_in[8];
    const float* WkO = (const float*)d_in[9];
    const float* WvO = (const float*)d_in[10];
    float* out = (float*)d_out;

    const int smem3 = 2 * 64 * SROW * (int)sizeof(__nv_bfloat16);
    cudaFuncSetAttribute(k_qeff, cudaFuncAttributeMaxDynamicSharedMemorySize, smem3);
    cudaFuncSetAttribute(k_main, cudaFuncAttributeMaxDynamicSharedMemorySize, SMEM_MAIN);

    k_wv  <<<24, 256>>>(WvT, WvR, WvO);
    k_vsum<<<NPT/8, 256>>>(feat);
    k_qeff<<<dim3(54, 4), 256, smem3>>>(qT, WkT, qR, WkR, qO, WkO);
    k_main<<<dim3(QG, NB, 2), 256, SMEM_MAIN>>>();
    k_final<<<(NB*PQ + 255)/256, 256>>>(out);
}